// round 2
// baseline (speedup 1.0000x reference)
#include <cuda_runtime.h>
#include <math.h>

#define NTOK 8192
#define DDIM 768
#define NEXP 16
#define D4   192          // DDIM/4 (float4 count per row of x / W)
#define GATE_BLOCKS 128   // 64 tokens per block
#define EPS  1e-5f

// ---------------- device scratch (no allocations allowed) ----------------
__device__ float4 g_gate[NTOK];                    // (w0, w1, e0 bits, e1 bits)
__device__ float  g_partials[GATE_BLOCKS * 32];    // per-block soft[16] + hard[16]
__device__ float  g_scratch[NTOK * NEXP + 64];     // fallback sink if out layout != full tuple

// ---------------- kernel 1: gate logits + top-2 softmax ----------------
// 128 blocks x 256 threads. W (48KB) staged in smem ONCE per block.
// 4 threads per token, each covering a 192-float quarter of D with 16
// register accumulators; shfl-reduce over the 4 lanes. sAcc (soft/hard
// partials) aliases the W smem after the last read (static smem = 48KB exact).
__global__ __launch_bounds__(256) void gate_kernel(
    const float* __restrict__ x,
    const float* __restrict__ W,
    const float* __restrict__ b,
    float* __restrict__ s_out)
{
    __shared__ float4 sW[3072];            // 48KB: W as float4 [e*192 + i]
    float* sAcc = (float*)sW;              // aliased AFTER last sW read

    const int tid = threadIdx.x;

    // stage W: 3072 float4, 12 per thread, coalesced
    const float4* W4 = (const float4*)W;
    #pragma unroll
    for (int i = tid; i < 3072; i += 256) sW[i] = W4[i];
    __syncthreads();

    const int tl = tid >> 2;               // local token 0..63
    const int q  = tid & 3;                // D-quarter 0..3
    const int n  = blockIdx.x * 64 + tl;

    float acc[NEXP];
    #pragma unroll
    for (int e = 0; e < NEXP; e++) acc[e] = 0.f;

    const float4* x4 = (const float4*)x;
    const size_t xbase = (size_t)n * D4 + q * 48;
    const int    wbase = q * 48;

    #pragma unroll 4
    for (int i = 0; i < 48; i++) {
        const float4 xv = x4[xbase + i];
        #pragma unroll
        for (int e = 0; e < NEXP; e++) {
            const float4 wv = sW[e * D4 + wbase + i];
            acc[e] += xv.x * wv.x + xv.y * wv.y + xv.z * wv.z + xv.w * wv.w;
        }
    }

    // reduce across the 4 quarter-lanes (lanes 4k..4k+3 share a token)
    #pragma unroll
    for (int e = 0; e < NEXP; e++) {
        acc[e] += __shfl_xor_sync(0xffffffffu, acc[e], 1);
        acc[e] += __shfl_xor_sync(0xffffffffu, acc[e], 2);
    }

    // per-token results live in q==0 threads; keep in regs across syncs
    float w0 = 0.f, w1 = 0.f;
    int   e0 = 0,   e1 = 0;
    if (q == 0) {
        float v[NEXP];
        #pragma unroll
        for (int e = 0; e < NEXP; e++) v[e] = acc[e] + b[e];

        float b0 = v[0], b1 = -INFINITY;
        e0 = 0; e1 = -1;
        #pragma unroll
        for (int e = 1; e < NEXP; e++) {
            if (v[e] > b0)      { b1 = b0; e1 = e0; b0 = v[e]; e0 = e; }
            else if (v[e] > b1) { b1 = v[e]; e1 = e; }
        }
        const float t   = expf(b1 - b0);
        const float inv = 1.f / (1.f + t);
        w0 = inv;
        w1 = t * inv;

        float4 gt;
        gt.x = w0; gt.y = w1;
        gt.z = __int_as_float(e0);
        gt.w = __int_as_float(e1);
        g_gate[n] = gt;

        // s_concat row: 1 where g < eps else 0 (g=0 for unselected)
        float4* srow = (float4*)(s_out + (size_t)n * NEXP);
        #pragma unroll
        for (int qq = 0; qq < 4; qq++) {
            float4 sv;
            #pragma unroll
            for (int c = 0; c < 4; c++) {
                const int e = qq * 4 + c;
                const float ge = (e == e0) ? w0 : ((e == e1) ? w1 : 0.f);
                const float val = (ge < EPS) ? 1.f : 0.f;
                if      (c == 0) sv.x = val;
                else if (c == 1) sv.y = val;
                else if (c == 2) sv.z = val;
                else             sv.w = val;
            }
            srow[qq] = sv;
        }
    }

    // ---- reuse sW smem as soft/hard accumulators ----
    __syncthreads();                       // everyone done reading sW
    if (tid < 32) sAcc[tid] = 0.f;
    __syncthreads();

    if (q == 0) {
        atomicAdd(&sAcc[e0], w0);
        atomicAdd(&sAcc[e1], w1);
        atomicAdd(&sAcc[16 + e0], (w0 < EPS) ? 0.f : 1.f);
        atomicAdd(&sAcc[16 + e1], (w1 < EPS) ? 0.f : 1.f);
    }
    __syncthreads();
    if (tid < 32) g_partials[blockIdx.x * 32 + tid] = sAcc[tid];
}

// ---------------- kernel 2: sparse combine (HBM-bound) ----------------
// One block per token; 384 threads x 2 elements. Loads the float4 quarter
// containing each selected expert (uniform per-block branch). When both
// experts share a quarter, one load serves both.
__device__ __forceinline__ float quad_get(const float4 v, const int c) {
    return (c == 0) ? v.x : (c == 1) ? v.y : (c == 2) ? v.z : v.w;
}

__global__ __launch_bounds__(384) void combine_kernel(
    const float* __restrict__ f,
    float* __restrict__ y)
{
    const int n = blockIdx.x;
    const float4 gt = g_gate[n];           // broadcast load
    const float w0 = gt.x, w1 = gt.y;
    const int   e0 = __float_as_int(gt.z);
    const int   e1 = __float_as_int(gt.w);
    const int   q0 = e0 >> 2, c0 = e0 & 3;
    const int   q1 = e1 >> 2, c1 = e1 & 3;

    const float4* fr4 = (const float4*)(f + (size_t)n * (DDIM * NEXP));
    float*        yr  = y + (size_t)n * DDIM;

    const int d0 = threadIdx.x;
    const int d1 = threadIdx.x + 384;

    if (q0 == q1) {                        // both experts in one float4 quarter
        const float4 a = __ldcs(&fr4[d0 * 4 + q0]);
        const float4 c = __ldcs(&fr4[d1 * 4 + q0]);
        yr[d0] = w0 * quad_get(a, c0) + w1 * quad_get(a, c1);
        yr[d1] = w0 * quad_get(c, c0) + w1 * quad_get(c, c1);
    } else {
        const float4 a0 = __ldcs(&fr4[d0 * 4 + q0]);
        const float4 a1 = __ldcs(&fr4[d0 * 4 + q1]);
        const float4 c0v = __ldcs(&fr4[d1 * 4 + q0]);
        const float4 c1v = __ldcs(&fr4[d1 * 4 + q1]);
        yr[d0] = w0 * quad_get(a0, c0) + w1 * quad_get(a1, c1);
        yr[d1] = w0 * quad_get(c0v, c0) + w1 * quad_get(c1v, c1);
    }
}

// ---------------- kernel 3: finalize averages + trailing scalar ----------------
__global__ void finalize_kernel(float* __restrict__ soft_out,
                                float* __restrict__ hard_out,
                                float* __restrict__ zero_out)
{
    const int tid = threadIdx.x;           // 32 threads
    float s = 0.f;
    for (int bb = 0; bb < GATE_BLOCKS; bb++)
        s += g_partials[bb * 32 + tid];
    s *= (1.f / (float)NTOK);
    if (tid < 16) soft_out[tid] = s;
    else          hard_out[tid - 16] = s;
    if (tid == 0) *zero_out = 0.f;
}

// ---------------- launcher ----------------
extern "C" void kernel_launch(void* const* d_in, const int* in_sizes, int n_in,
                              void* d_out, int out_size)
{
    const float* f = (const float*)d_in[0];
    const float* x = (const float*)d_in[1];
    const float* W = (const float*)d_in[2];
    const float* b = (const float*)d_in[3];
    float* out = (float*)d_out;

    float* scratch = nullptr;
    cudaGetSymbolAddress((void**)&scratch, g_scratch);

    // flattened tuple layout: y | soft | hard | s_concat | 0
    const int FULL = NTOK * DDIM + 16 + 16 + NTOK * NEXP + 1;   // 6422561
    float *y, *soft, *hard, *sc, *zero;
    if (out_size == FULL) {
        y    = out;
        soft = out + NTOK * DDIM;
        hard = soft + 16;
        sc   = hard + 16;
        zero = sc + NTOK * NEXP;
    } else {
        y    = out;
        sc   = scratch;
        soft = scratch + NTOK * NEXP;
        hard = soft + 16;
        zero = hard + 16;
    }

    gate_kernel<<<GATE_BLOCKS, 256>>>(x, W, b, sc);
    combine_kernel<<<NTOK, 384>>>(f, y);
    finalize_kernel<<<1, 32>>>(soft, hard, zero);
}